// round 14
// baseline (speedup 1.0000x reference)
#include <cuda_runtime.h>
#include <cuda_bf16.h>
#include <math.h>
#include <stdint.h>

#define B_   4
#define T_   1024
#define D_   512
#define H_   2048
#define L_   6
#define WIN  64
#define MT   (B_*T_)          // 4096 rows
#define NBTD (B_*T_*D_)       // 2,097,152

#define WL   (4*D_*D_ + D_*H_ + H_*D_)
#define OFF_WQ 0
#define OFF_WK (D_*D_)
#define OFF_WV (2*D_*D_)
#define OFF_WO (3*D_*D_)
#define OFF_W1 (4*D_*D_)
#define OFF_W2 (4*D_*D_ + D_*H_)

// ---------------- scratch (static __device__, alloc-free) ----------------
__device__ __align__(16) float g_E[NBTD];
__device__ __align__(16) float g_QKV[3*NBTD];
__device__ __align__(16) float g_A[NBTD];
__device__ __align__(16) float g_AOf[NBTD];
__device__ __align__(16) __nv_bfloat16 g_Eh[NBTD],  g_El[NBTD];
__device__ __align__(16) __nv_bfloat16 g_Yh[NBTD],  g_Yl[NBTD];
__device__ __align__(16) __nv_bfloat16 g_AOh[NBTD], g_AOl[NBTD];
__device__ __align__(16) __nv_bfloat16 g_F1h[MT*H_], g_F1l[MT*H_];
__device__ __align__(16) __nv_bfloat16 g_Wth[L_*WL], g_Wtl[L_*WL];
__device__ __align__(16) float g_bpack[L_*3*D_];
__device__ float g_ew[L_*T_*WIN];
__device__ float g_kpart[B_*32*D_];
__device__ float g_kmax[B_*D_];

// ---------------- helpers ----------------
__device__ __forceinline__ void split2(float x, __nv_bfloat16* h, __nv_bfloat16* l) {
    __nv_bfloat16 hh = __float2bfloat16(x);
    *h = hh;
    *l = __float2bfloat16(x - __bfloat162float(hh));
}
__device__ __forceinline__ uint32_t smem_u32(const void* p) {
    uint32_t a;
    asm("{ .reg .u64 t; cvta.to.shared.u64 t, %1; cvt.u32.u64 %0, t; }" : "=r"(a) : "l"(p));
    return a;
}
__device__ __forceinline__ void cpa16(uint32_t s, const void* g) {
    asm volatile("cp.async.cg.shared.global [%0], [%1], 16;" :: "r"(s), "l"(g));
}
__device__ __forceinline__ void ldmx4(uint32_t* r, uint32_t addr) {
    asm volatile("ldmatrix.sync.aligned.m8n8.x4.shared.b16 {%0,%1,%2,%3}, [%4];"
        : "=r"(r[0]), "=r"(r[1]), "=r"(r[2]), "=r"(r[3]) : "r"(addr));
}
__device__ __forceinline__ void mma16816(float* c, const uint32_t* a, uint32_t b0, uint32_t b1) {
    asm volatile("mma.sync.aligned.m16n8k16.row.col.f32.bf16.bf16.f32 "
        "{%0,%1,%2,%3}, {%4,%5,%6,%7}, {%8,%9}, {%0,%1,%2,%3};"
        : "+f"(c[0]), "+f"(c[1]), "+f"(c[2]), "+f"(c[3])
        : "r"(a[0]), "r"(a[1]), "r"(a[2]), "r"(a[3]), "r"(b0), "r"(b1));
}

// ---------------- HMMA GEMM: 256 threads, 8 warps, warp tile 32x64 ----------------
// 3-stage pipeline, 96KB smem -> 2 CTAs/SM. Term-major MMA ordering: 16
// independent accumulators between same-acc reuses (hides HMMA latency).
#define STAGES 3
#define SSTAGE 32768
#define SA_H 0
#define SA_L 8192
#define SB_H 16384
#define SB_L 24576
#define DSM_BYTES (STAGES*SSTAGE)

template<int RELU, int OUTF, int OUTB>
__global__ void __launch_bounds__(256, 2)
tc_gemm(const __nv_bfloat16* __restrict__ Ah_, const __nv_bfloat16* __restrict__ Al_,
        const __nv_bfloat16* __restrict__ Bh_, const __nv_bfloat16* __restrict__ Bl_,
        const float* __restrict__ bias_, float* Cf_,
        __nv_bfloat16* Ch_, __nv_bfloat16* Cl_,
        int M, int N, int K, long sB, long sBias, long sC) {
    extern __shared__ __align__(1024) char dsm[];
    int t = threadIdx.x;
    int wid = t >> 5, l = t & 31;
    int wy = wid & 3, wx = wid >> 2;       // warp tile: rows wy*32, cols wx*64
    int z = blockIdx.z;
    int bn = blockIdx.x * 128, bm = blockIdx.y * 128;

    const __nv_bfloat16* Ahp = Ah_;
    const __nv_bfloat16* Alp = Al_;
    const __nv_bfloat16* Bhp = Bh_ + (long)z * sB;
    const __nv_bfloat16* Blp = Bl_ + (long)z * sB;
    const float* bias = bias_ + (long)z * sBias;
    float* Cf = Cf_ ? (Cf_ + (long)z * sC) : nullptr;

    uint32_t sbase = smem_u32(dsm);

    int ra = t >> 2, kb = t & 3;
    int rb2 = ra + 64;
    long gA0 = (long)(bm + ra)  * K + kb * 8;
    long gA1 = (long)(bm + rb2) * K + kb * 8;
    long gB0 = (long)(bn + ra)  * K + kb * 8;
    long gB1 = (long)(bn + rb2) * K + kb * 8;
    uint32_t sO0 = (uint32_t)((ra  >> 3) * 512 + kb * 128 + (ra  & 7) * 16);
    uint32_t sO1 = (uint32_t)((rb2 >> 3) * 512 + kb * 128 + (rb2 & 7) * 16);

    auto load_stage = [&](int st, int kc) {
        uint32_t sb = sbase + st * SSTAGE;
        cpa16(sb + SA_H + sO0, Ahp + gA0 + kc);
        cpa16(sb + SA_H + sO1, Ahp + gA1 + kc);
        cpa16(sb + SA_L + sO0, Alp + gA0 + kc);
        cpa16(sb + SA_L + sO1, Alp + gA1 + kc);
        cpa16(sb + SB_H + sO0, Bhp + gB0 + kc);
        cpa16(sb + SB_H + sO1, Bhp + gB1 + kc);
        cpa16(sb + SB_L + sO0, Blp + gB0 + kc);
        cpa16(sb + SB_L + sO1, Blp + gB1 + kc);
    };

    uint32_t lr = (uint32_t)((l & 7) * 16);
    uint32_t offA[2][2], offB[4][2];
#pragma unroll
    for (int mi = 0; mi < 2; mi++)
#pragma unroll
        for (int ks = 0; ks < 2; ks++) {
            int tr = wy*4 + mi*2 + ((l >> 3) & 1);
            int tk = ks*2 + ((l >> 4) & 1);
            offA[mi][ks] = (uint32_t)((tr*4 + tk) * 128) + lr;
        }
#pragma unroll
    for (int j = 0; j < 4; j++)
#pragma unroll
        for (int ks = 0; ks < 2; ks++) {
            int tn = wx*8 + 2*j + ((l >> 4) & 1);
            int tk = ks*2 + ((l >> 3) & 1);
            offB[j][ks] = (uint32_t)((tn*4 + tk) * 128) + lr;
        }

    int nk = K >> 5;
    load_stage(0, 0);   asm volatile("cp.async.commit_group;");
    load_stage(1, 32);  asm volatile("cp.async.commit_group;");
    asm volatile("cp.async.wait_group 1;");
    __syncthreads();

    float acc[2][8][4] = {};

    int st_c = 0;
    int st_l = 2;
    for (int kt = 0; kt < nk; kt++) {
        if (kt + 2 < nk) load_stage(st_l, (kt + 2) * 32);
        asm volatile("cp.async.commit_group;");

        uint32_t sb = sbase + st_c * SSTAGE;
#pragma unroll
        for (int ks = 0; ks < 2; ks++) {
            uint32_t ah[2][4], al[2][4], bh[4][4], bl[4][4];
#pragma unroll
            for (int mi = 0; mi < 2; mi++) {
                ldmx4(ah[mi], sb + SA_H + offA[mi][ks]);
                ldmx4(al[mi], sb + SA_L + offA[mi][ks]);
            }
#pragma unroll
            for (int j = 0; j < 4; j++) {
                ldmx4(bh[j], sb + SB_H + offB[j][ks]);
                ldmx4(bl[j], sb + SB_L + offB[j][ks]);
            }
            // term-major: all 16 accs touched once per term -> reuse distance 16
#pragma unroll
            for (int mi = 0; mi < 2; mi++)
#pragma unroll
                for (int j = 0; j < 4; j++) {
                    mma16816(acc[mi][2*j],   ah[mi], bh[j][0], bh[j][1]);
                    mma16816(acc[mi][2*j+1], ah[mi], bh[j][2], bh[j][3]);
                }
#pragma unroll
            for (int mi = 0; mi < 2; mi++)
#pragma unroll
                for (int j = 0; j < 4; j++) {
                    mma16816(acc[mi][2*j],   ah[mi], bl[j][0], bl[j][1]);
                    mma16816(acc[mi][2*j+1], ah[mi], bl[j][2], bl[j][3]);
                }
#pragma unroll
            for (int mi = 0; mi < 2; mi++)
#pragma unroll
                for (int j = 0; j < 4; j++) {
                    mma16816(acc[mi][2*j],   al[mi], bh[j][0], bh[j][1]);
                    mma16816(acc[mi][2*j+1], al[mi], bh[j][2], bh[j][3]);
                }
        }
        asm volatile("cp.async.wait_group 1;");
        __syncthreads();
        st_c = (st_c == 2) ? 0 : st_c + 1;
        st_l = (st_l == 2) ? 0 : st_l + 1;
    }

    int gid = l >> 2, tg = l & 3;
#pragma unroll
    for (int mi = 0; mi < 2; mi++) {
        int row0 = bm + wy*32 + mi*16 + gid;
#pragma unroll
        for (int nt = 0; nt < 8; nt++) {
            int col = bn + wx*64 + nt*8 + tg*2;
            float b0v = bias[col], b1v = bias[col + 1];
            float v00 = acc[mi][nt][0] + b0v, v01 = acc[mi][nt][1] + b1v;
            float v10 = acc[mi][nt][2] + b0v, v11 = acc[mi][nt][3] + b1v;
            if (RELU) {
                v00 = fmaxf(v00, 0.f); v01 = fmaxf(v01, 0.f);
                v10 = fmaxf(v10, 0.f); v11 = fmaxf(v11, 0.f);
            }
            long i0 = (long)row0 * N + col;
            long i1 = (long)(row0 + 8) * N + col;
            if (OUTF) {
                *(float2*)&Cf[i0] = make_float2(v00, v01);
                *(float2*)&Cf[i1] = make_float2(v10, v11);
            }
            if (OUTB) {
                __nv_bfloat16 h0, l0, h1, l1;
                split2(v00, &h0, &l0); split2(v01, &h1, &l1);
                *(__nv_bfloat162*)&Ch_[i0] = __nv_bfloat162(h0, h1);
                *(__nv_bfloat162*)&Cl_[i0] = __nv_bfloat162(l0, l1);
                split2(v10, &h0, &l0); split2(v11, &h1, &l1);
                *(__nv_bfloat162*)&Ch_[i1] = __nv_bfloat162(h0, h1);
                *(__nv_bfloat162*)&Cl_[i1] = __nv_bfloat162(l0, l1);
            }
        }
    }
}

// ---------------- single merged weight prep ----------------
__device__ __forceinline__ void wsplit_tile_xy(const float* __restrict__ W,
                                               __nv_bfloat16* __restrict__ oh,
                                               __nv_bfloat16* __restrict__ ol,
                                               int K, int N, int tx32, int ty32) {
    __shared__ float s[32][33];
    int bx = tx32 * 32, by = ty32 * 32;
    int tx = threadIdx.x, ty = threadIdx.y;
#pragma unroll
    for (int r = 0; r < 32; r += 8)
        s[ty + r][tx] = W[(long)(by + ty + r) * N + bx + tx];
    __syncthreads();
#pragma unroll
    for (int r = 0; r < 32; r += 8) {
        float v = s[tx][ty + r];
        long o = (long)(bx + ty + r) * K + by + tx;
        split2(v, &oh[o], &ol[o]);
    }
}

__global__ void k_wsplit_all(const float* __restrict__ Wq, const float* __restrict__ Wk,
                             const float* __restrict__ Wv, const float* __restrict__ Wo,
                             const float* __restrict__ W1, const float* __restrict__ W2,
                             __nv_bfloat16* __restrict__ oh, __nv_bfloat16* __restrict__ ol) {
    int z = blockIdx.z, l = z / 6, w = z % 6;
    long lo = (long)l * WL;
    if (w < 4) {
        if (blockIdx.x >= 16) return;
        const float* W = (w == 0 ? Wq : w == 1 ? Wk : w == 2 ? Wv : Wo) + (long)l * D_ * D_;
        wsplit_tile_xy(W, oh + lo + (long)w * D_ * D_, ol + lo + (long)w * D_ * D_,
                       D_, D_, blockIdx.x, blockIdx.y);
    } else if (w == 4) {
        wsplit_tile_xy(W1 + (long)l * D_ * H_, oh + lo + OFF_W1, ol + lo + OFF_W1,
                       D_, H_, blockIdx.x, blockIdx.y);
    } else {
        wsplit_tile_xy(W2 + (long)l * H_ * D_, oh + lo + OFF_W2, ol + lo + OFF_W2,
                       H_, D_, blockIdx.y, blockIdx.x);
    }
}

__global__ void k_bpack(const float* __restrict__ bq, const float* __restrict__ bk,
                        const float* __restrict__ bv, float* __restrict__ out) {
    int i = blockIdx.x * 256 + threadIdx.x;
    if (i >= L_ * 3 * D_) return;
    int l = i / (3 * D_), r = (i / D_) % 3, d = i % D_;
    const float* s = (r == 0) ? bq : (r == 1) ? bk : bv;
    out[i] = s[l * D_ + d];
}

// ---------------- embedding, fused ----------------
__global__ void k_embed2(const int* __restrict__ x, const float* __restrict__ tok,
                         const float* __restrict__ pos, float* __restrict__ h,
                         float* __restrict__ e, __nv_bfloat16* __restrict__ eh,
                         __nv_bfloat16* __restrict__ el) {
    int i = blockIdx.x * blockDim.x + threadIdx.x;
    if (i >= NBTD) return;
    int d = i % D_, bt = i / D_, t = bt % T_;
    float s = rsqrtf((float)D_);
    float p = pos[t * D_ + d] * s;
    float hv = tok[(long)x[bt] * D_ + d] * s + p;
    h[i] = hv;
    float ev = hv + p;
    e[i] = ev;
    split2(ev, &eh[i], &el[i]);
}

__global__ void k_ew_all(const float* __restrict__ wb, float* __restrict__ ew) {
    int t = blockIdx.x, li = blockIdx.y, j = threadIdx.x;
    bool valid = (j <= t);
    float w = valid ? wb[(long)li*T_*T_ + (long)t*T_ + (t - j)] : -1e30f;
    __shared__ float sm[64];
    sm[j] = w; __syncthreads();
    for (int off = 32; off > 0; off >>= 1) {
        if (j < off) sm[j] = fmaxf(sm[j], sm[j + off]);
        __syncthreads();
    }
    ew[(long)li*T_*WIN + t*WIN + j] = valid ? expf(w - sm[0]) : 0.f;
}

__global__ void k_kmax_part(const float* __restrict__ K, float* __restrict__ part) {
    int b = blockIdx.y, z = blockIdx.x, d = threadIdx.x;
    float m = -INFINITY;
    int t0 = z * (T_/32);
#pragma unroll 4
    for (int t = t0; t < t0 + T_/32; t++)
        m = fmaxf(m, K[((long)b*T_ + t)*D_ + d]);
    part[(b*32 + z)*D_ + d] = m;
}
__global__ void k_kmax_red(const float* __restrict__ part, float* __restrict__ kmax) {
    int b = blockIdx.x, d = threadIdx.x;
    float m = -INFINITY;
#pragma unroll
    for (int z = 0; z < 32; z++) m = fmaxf(m, part[(b*32 + z)*D_ + d]);
    kmax[b*D_ + d] = m;
}

// ---------------- tiled banded AFT ----------------
#define TBB 64
#define DBB 32
__global__ void __launch_bounds__(256, 3)
k_band3(const float* __restrict__ Qf, const float* __restrict__ Kf,
        const float* __restrict__ Vf, const float* __restrict__ kmax,
        const float* __restrict__ ew,
        __nv_bfloat16* __restrict__ Yh, __nv_bfloat16* __restrict__ Yl) {
    __shared__ float2 sp[127 * DBB];
    __shared__ float  sw[TBB * WIN];
    int t0 = blockIdx.x * TBB;
    int b  = blockIdx.y;
    int d0 = blockIdx.z * DBB;
    int tid = threadIdx.x;

    for (int i = tid; i < 127 * DBB; i += 256) {
        int r = i / DBB, dd = i % DBB;
        int u = t0 - 63 + r;
        if (u >= 0) {
            long idx = ((long)b*T_ + u)*D_ + d0 + dd;
            float ek = expf(Kf[idx] - kmax[b*D_ + d0 + dd]);
            sp[i] = make_float2(ek, ek * Vf[idx]);
        } else {
            sp[i] = make_float2(0.f, 0.f);
        }
    }
    for (int i = tid; i < TBB * WIN; i += 256)
        sw[i] = ew[(long)(t0 + i/WIN)*WIN + (i % WIN)];
    __syncthreads();

    int dd = tid & 31, tq = tid >> 5;
    int tb = tq * 8;

    float2 win[8];
#pragma unroll
    for (int i = 0; i < 8; i++) win[i] = sp[(tb + i + 63)*DBB + dd];

    float num[8] = {}, den[8] = {};
#pragma unroll 8
    for (int j = 0; j < WIN; j++) {
#pragma unroll
        for (int i = 0; i < 8; i++) {
            float w = sw[(tb + i)*WIN + j];
            num[i] = fmaf(w, win[i].y, num[i]);
            den[i] = fmaf(w, win[i].x, den[i]);
        }
        if (j < WIN - 1) {
#pragma unroll
            for (int i = 7; i >= 1; i--) win[i] = win[i-1];
            win[0] = sp[(tb + 62 - j)*DBB + dd];
        }
    }

#pragma unroll
    for (int i = 0; i < 8; i++) {
        int t = t0 + tb + i;
        long idx = ((long)b*T_ + t)*D_ + d0 + dd;
        float q = Qf[idx];
        float sig = 1.f / (1.f + expf(-q));
        float y = sig * num[i] / (den[i] + 1e-9f);
        split2(y, &Yh[idx], &Yl[idx]);
    }
}

// ---------------- LayerNorm(X + R), optional pos-fusion ----------------
template<int OUTB, int POS>
__global__ void k_resid_ln(const float* __restrict__ X, const float* __restrict__ R,
                           const float* __restrict__ g, const float* __restrict__ bta,
                           float* __restrict__ out,
                           __nv_bfloat16* __restrict__ oh, __nv_bfloat16* __restrict__ ol,
                           const float* __restrict__ pos, float* __restrict__ e) {
    int row = blockIdx.x, tid = threadIdx.x;
    long base = (long)row * D_;
    float x0 = X[base + tid]       + R[base + tid];
    float x1 = X[base + tid + 256] + R[base + tid + 256];
    __shared__ float2 red[256];
    red[tid] = make_float2(x0 + x1, x0*x0 + x1*x1);
    __syncthreads();
    for (int off = 128; off > 0; off >>= 1) {
        if (tid < off) {
            red[tid].x += red[tid+off].x;
            red[tid].y += red[tid+off].y;
        }
        __syncthreads();
    }
    float mean = red[0].x * (1.f/D_);
    float var  = red[0].y * (1.f/D_) - mean*mean;
    float rs = rsqrtf(var + 1e-5f);
    float o0 = (x0 - mean)*rs*g[tid]       + bta[tid];
    float o1 = (x1 - mean)*rs*g[tid + 256] + bta[tid + 256];
    out[base + tid]       = o0;
    out[base + tid + 256] = o1;
    if (POS) {
        int t = row % T_;
        float s = rsqrtf((float)D_);
        float e0 = o0 + pos[(long)t*D_ + tid] * s;
        float e1 = o1 + pos[(long)t*D_ + tid + 256] * s;
        e[base + tid]       = e0;
        e[base + tid + 256] = e1;
        split2(e0, &oh[base + tid],       &ol[base + tid]);
        split2(e1, &oh[base + tid + 256], &ol[base + tid + 256]);
    } else if (OUTB) {
        split2(o0, &oh[base + tid],       &ol[base + tid]);
        split2(o1, &oh[base + tid + 256], &ol[base + tid + 256]);
    }
}

// ---------------- orchestration ----------------
extern "C" void kernel_launch(void* const* d_in, const int* in_sizes, int n_in,
                              void* d_out, int out_size) {
    const int*   x     = (const int*)  d_in[0];
    const float* tok   = (const float*)d_in[1];
    const float* pos   = (const float*)d_in[2];
    const float* Wq    = (const float*)d_in[3];
    const float* bq    = (const float*)d_in[4];
    const float* Wk    = (const float*)d_in[5];
    const float* bk    = (const float*)d_in[6];
    const float* Wv    = (const float*)d_in[7];
    const float* bv    = (const float*)d_in[8];
    const float* Wo    = (const float*)d_in[9];
    const float* bo    = (const float*)d_in[10];
    const float* wbias = (const float*)d_in[11];
    const float* lng   = (const float*)d_in[12];
    const float* lnb   = (const float*)d_in[13];
    const float* W1    = (const float*)d_in[14];
    const float* b1    = (const float*)d_in[15];
    const float* W2    = (const float*)d_in[16];
    const float* b2    = (const float*)d_in[17];
    float* H = (float*)d_out;

    float *E, *QKV, *A, *AOf, *EW, *KP, *KM, *BP;
    __nv_bfloat16 *Eh, *El, *Yh, *Yl, *AOh, *AOl, *F1h, *F1l, *Wth, *Wtl;
    cudaGetSymbolAddress((void**)&E,   g_E);
    cudaGetSymbolAddress((void**)&QKV, g_QKV);
    cudaGetSymbolAddress((void**)&A,   g_A);
    cudaGetSymbolAddress((void**)&AOf, g_AOf);
    cudaGetSymbolAddress((void**)&EW,  g_ew);
    cudaGetSymbolAddress((void**)&KP,  g_kpart);
    cudaGetSymbolAddress((void**)&KM,  g_kmax);
    cudaGetSymbolAddress((void**)&BP,  g_bpack);
    cudaGetSymbolAddress((void**)&Eh,  g_Eh);  cudaGetSymbolAddress((void**)&El,  g_El);
    cudaGetSymbolAddress((void**)&Yh,  g_Yh);  cudaGetSymbolAddress((void**)&Yl,  g_Yl);
    cudaGetSymbolAddress((void**)&AOh, g_AOh); cudaGetSymbolAddress((void**)&AOl, g_AOl);
    cudaGetSymbolAddress((void**)&F1h, g_F1h); cudaGetSymbolAddress((void**)&F1l, g_F1l);
    cudaGetSymbolAddress((void**)&Wth, g_Wth); cudaGetSymbolAddress((void**)&Wtl, g_Wtl);

    cudaFuncSetAttribute(tc_gemm<0,1,0>, cudaFuncAttributeMaxDynamicSharedMemorySize, DSM_BYTES);
    cudaFuncSetAttribute(tc_gemm<1,0,1>, cudaFuncAttributeMaxDynamicSharedMemorySize, DSM_BYTES);

    const int EL_BLK = 256;
    const int EL_GRID = (NBTD + EL_BLK - 1) / EL_BLK;
    dim3 wblk(32, 8);

    float* Qf = QKV;
    float* Kf = QKV + (long)NBTD;
    float* Vf = QKV + 2L*NBTD;

    // launch 1..3: prep; launch 4 = layer-0 QKV GEMM (ncu window target)
    k_wsplit_all<<<dim3(64, 16, L_*6), wblk>>>(Wq, Wk, Wv, Wo, W1, W2, Wth, Wtl);
    k_bpack<<<(L_*3*D_ + 255)/256, 256>>>(bq, bk, bv, BP);
    k_embed2<<<EL_GRID, EL_BLK>>>(x, tok, pos, H, E, Eh, El);

    bool ew_done = false;

    for (int l = 0; l < L_; l++) {
        long lo = (long)l * WL;
        const float* gi  = lng + l*D_;
        const float* bi  = lnb + l*D_;

        tc_gemm<0,1,0><<<dim3(D_/128, MT/128, 3), 256, DSM_BYTES>>>(
            Eh, El, Wth + lo, Wtl + lo, BP + (long)l*3*D_,
            QKV, nullptr, nullptr, MT, D_, D_,
            (long)D_*D_, (long)D_, (long)NBTD);

        if (!ew_done) {
            k_ew_all<<<dim3(T_, L_), WIN>>>(wbias, EW);
            ew_done = true;
        }

        k_kmax_part<<<dim3(32, B_), D_>>>(Kf, KP);
        k_kmax_red<<<B_, D_>>>(KP, KM);

        k_band3<<<dim3(T_/TBB, B_, D_/DBB), 256>>>(Qf, Kf, Vf, KM, EW + (long)l*T_*WIN, Yh, Yl);

        tc_gemm<0,1,0><<<dim3(D_/128, MT/128, 1), 256, DSM_BYTES>>>(
            Yh, Yl, Wth + lo + OFF_WO, Wtl + lo + OFF_WO, bo + (long)l*D_,
            A, nullptr, nullptr, MT, D_, D_, 0, 0, 0);

        k_resid_ln<1,0><<<MT, 256>>>(A, E, gi, bi, AOf, AOh, AOl, nullptr, nullptr);

        tc_gemm<1,0,1><<<dim3(H_/128, MT/128, 1), 256, DSM_BYTES>>>(
            AOh, AOl, Wth + lo + OFF_W1, Wtl + lo + OFF_W1, b1 + (long)l*H_,
            nullptr, F1h, F1l, MT, H_, D_, 0, 0, 0);

        tc_gemm<0,1,0><<<dim3(D_/128, MT/128, 1), 256, DSM_BYTES>>>(
            F1h, F1l, Wth + lo + OFF_W2, Wtl + lo + OFF_W2, b2 + (long)l*D_,
            A, nullptr, nullptr, MT, D_, H_, 0, 0, 0);

        if (l < L_ - 1) {
            k_resid_ln<1,1><<<MT, 256>>>(A, AOf, gi, bi, H, Eh, El, pos, E);
        } else {
            k_resid_ln<0,0><<<MT, 256>>>(A, AOf, gi, bi, H, nullptr, nullptr, nullptr, nullptr);
        }
    }
}

// round 15
// speedup vs baseline: 1.3305x; 1.3305x over previous
#include <cuda_runtime.h>
#include <cuda_fp16.h>
#include <math.h>
#include <stdint.h>

#define B_   4
#define T_   1024
#define D_   512
#define H_   2048
#define L_   6
#define WIN  64
#define MT   (B_*T_)          // 4096 rows
#define NBTD (B_*T_*D_)       // 2,097,152

#define WL   (4*D_*D_ + D_*H_ + H_*D_)
#define OFF_WQ 0
#define OFF_WK (D_*D_)
#define OFF_WV (2*D_*D_)
#define OFF_WO (3*D_*D_)
#define OFF_W1 (4*D_*D_)
#define OFF_W2 (4*D_*D_ + D_*H_)

// ---------------- scratch (static __device__, alloc-free) ----------------
__device__ __align__(16) float g_E[NBTD];
__device__ __align__(16) float g_QKV[3*NBTD];
__device__ __align__(16) float g_A[NBTD];
__device__ __align__(16) float g_AOf[NBTD];
__device__ __align__(16) __half g_Eh[NBTD],  g_El[NBTD];
__device__ __align__(16) __half g_Yh[NBTD],  g_Yl[NBTD];
__device__ __align__(16) __half g_AOh[NBTD], g_AOl[NBTD];
__device__ __align__(16) __half g_F1h[MT*H_], g_F1l[MT*H_];
__device__ __align__(16) __half g_Wth[L_*WL];      // weights: single fp16
__device__ __align__(16) float g_bpack[L_*3*D_];
__device__ float g_ew[L_*T_*WIN];
__device__ float g_kpart[B_*32*D_];
__device__ float g_kmax[B_*D_];

// ---------------- helpers ----------------
__device__ __forceinline__ void split2h(float x, __half* h, __half* l) {
    __half hh = __float2half_rn(x);
    *h = hh;
    *l = __float2half_rn(x - __half2float(hh));
}
__device__ __forceinline__ uint32_t smem_u32(const void* p) {
    uint32_t a;
    asm("{ .reg .u64 t; cvta.to.shared.u64 t, %1; cvt.u32.u64 %0, t; }" : "=r"(a) : "l"(p));
    return a;
}
__device__ __forceinline__ void cpa16(uint32_t s, const void* g) {
    asm volatile("cp.async.cg.shared.global [%0], [%1], 16;" :: "r"(s), "l"(g));
}
__device__ __forceinline__ void ldmx4(uint32_t* r, uint32_t addr) {
    asm volatile("ldmatrix.sync.aligned.m8n8.x4.shared.b16 {%0,%1,%2,%3}, [%4];"
        : "=r"(r[0]), "=r"(r[1]), "=r"(r[2]), "=r"(r[3]) : "r"(addr));
}
__device__ __forceinline__ void mma16816h(float* c, const uint32_t* a, uint32_t b0, uint32_t b1) {
    asm volatile("mma.sync.aligned.m16n8k16.row.col.f32.f16.f16.f32 "
        "{%0,%1,%2,%3}, {%4,%5,%6,%7}, {%8,%9}, {%0,%1,%2,%3};"
        : "+f"(c[0]), "+f"(c[1]), "+f"(c[2]), "+f"(c[3])
        : "r"(a[0]), "r"(a[1]), "r"(a[2]), "r"(a[3]), "r"(b0), "r"(b1));
}

// ---------------- HMMA GEMM: 2-term fp16 (A split hi/lo, B single) ----------------
// 256 threads, 8 warps (warp tile 32x64), 4-stage pipeline, 96KB smem -> 2 CTAs/SM.
#define STAGES 4
#define SSTAGE 24576
#define SA_H 0
#define SA_L 8192
#define SB_  16384
#define DSM_BYTES (STAGES*SSTAGE)

template<int RELU, int OUTF, int OUTB>
__global__ void __launch_bounds__(256, 2)
tc_gemm(const __half* __restrict__ Ah_, const __half* __restrict__ Al_,
        const __half* __restrict__ Bh_,
        const float* __restrict__ bias_, float* Cf_,
        __half* Ch_, __half* Cl_,
        int M, int N, int K, long sB, long sBias, long sC) {
    extern __shared__ __align__(1024) char dsm[];
    int t = threadIdx.x;
    int wid = t >> 5, l = t & 31;
    int wy = wid & 3, wx = wid >> 2;       // warp tile: rows wy*32, cols wx*64
    int z = blockIdx.z;
    int bn = blockIdx.x * 128, bm = blockIdx.y * 128;

    const __half* Ahp = Ah_;
    const __half* Alp = Al_;
    const __half* Bhp = Bh_ + (long)z * sB;
    const float* bias = bias_ + (long)z * sBias;
    float* Cf = Cf_ ? (Cf_ + (long)z * sC) : nullptr;

    uint32_t sbase = smem_u32(dsm);

    // cp.async mapping: 256 threads, 2 rows per sub-tile per thread
    int ra = t >> 2, kb = t & 3;
    int rb2 = ra + 64;
    long gA0 = (long)(bm + ra)  * K + kb * 8;
    long gA1 = (long)(bm + rb2) * K + kb * 8;
    long gB0 = (long)(bn + ra)  * K + kb * 8;
    long gB1 = (long)(bn + rb2) * K + kb * 8;
    uint32_t sO0 = (uint32_t)((ra  >> 3) * 512 + kb * 128 + (ra  & 7) * 16);
    uint32_t sO1 = (uint32_t)((rb2 >> 3) * 512 + kb * 128 + (rb2 & 7) * 16);

    auto load_stage = [&](int st, int kc) {
        uint32_t sb = sbase + st * SSTAGE;
        cpa16(sb + SA_H + sO0, Ahp + gA0 + kc);
        cpa16(sb + SA_H + sO1, Ahp + gA1 + kc);
        cpa16(sb + SA_L + sO0, Alp + gA0 + kc);
        cpa16(sb + SA_L + sO1, Alp + gA1 + kc);
        cpa16(sb + SB_  + sO0, Bhp + gB0 + kc);
        cpa16(sb + SB_  + sO1, Bhp + gB1 + kc);
    };

    uint32_t lr = (uint32_t)((l & 7) * 16);
    uint32_t offA[2][2], offB[4][2];
#pragma unroll
    for (int mi = 0; mi < 2; mi++)
#pragma unroll
        for (int ks = 0; ks < 2; ks++) {
            int tr = wy*4 + mi*2 + ((l >> 3) & 1);
            int tk = ks*2 + ((l >> 4) & 1);
            offA[mi][ks] = (uint32_t)((tr*4 + tk) * 128) + lr;
        }
#pragma unroll
    for (int j = 0; j < 4; j++)
#pragma unroll
        for (int ks = 0; ks < 2; ks++) {
            int tn = wx*8 + 2*j + ((l >> 4) & 1);
            int tk = ks*2 + ((l >> 3) & 1);
            offB[j][ks] = (uint32_t)((tn*4 + tk) * 128) + lr;
        }

    int nk = K >> 5;
    load_stage(0, 0);   asm volatile("cp.async.commit_group;");
    load_stage(1, 32);  asm volatile("cp.async.commit_group;");
    load_stage(2, 64);  asm volatile("cp.async.commit_group;");
    asm volatile("cp.async.wait_group 2;");
    __syncthreads();

    float acc[2][8][4] = {};

    for (int kt = 0; kt < nk; kt++) {
        if (kt + 3 < nk) load_stage((kt + 3) & 3, (kt + 3) * 32);
        asm volatile("cp.async.commit_group;");

        uint32_t sb = sbase + (kt & 3) * SSTAGE;
#pragma unroll
        for (int ks = 0; ks < 2; ks++) {
            uint32_t ah[2][4], al[2][4], bb[4][4];
#pragma unroll
            for (int mi = 0; mi < 2; mi++) {
                ldmx4(ah[mi], sb + SA_H + offA[mi][ks]);
                ldmx4(al[mi], sb + SA_L + offA[mi][ks]);
            }
#pragma unroll
            for (int j = 0; j < 4; j++)
                ldmx4(bb[j], sb + SB_ + offB[j][ks]);
#pragma unroll
            for (int mi = 0; mi < 2; mi++)
#pragma unroll
                for (int j = 0; j < 4; j++) {
                    mma16816h(acc[mi][2*j],   ah[mi], bb[j][0], bb[j][1]);
                    mma16816h(acc[mi][2*j+1], ah[mi], bb[j][2], bb[j][3]);
                    mma16816h(acc[mi][2*j],   al[mi], bb[j][0], bb[j][1]);
                    mma16816h(acc[mi][2*j+1], al[mi], bb[j][2], bb[j][3]);
                }
        }
        asm volatile("cp.async.wait_group 2;");
        __syncthreads();
    }

    int gid = l >> 2, tg = l & 3;
#pragma unroll
    for (int mi = 0; mi < 2; mi++) {
        int row0 = bm + wy*32 + mi*16 + gid;
#pragma unroll
        for (int nt = 0; nt < 8; nt++) {
            int col = bn + wx*64 + nt*8 + tg*2;
            float b0v = bias[col], b1v = bias[col + 1];
            float v00 = acc[mi][nt][0] + b0v, v01 = acc[mi][nt][1] + b1v;
            float v10 = acc[mi][nt][2] + b0v, v11 = acc[mi][nt][3] + b1v;
            if (RELU) {
                v00 = fmaxf(v00, 0.f); v01 = fmaxf(v01, 0.f);
                v10 = fmaxf(v10, 0.f); v11 = fmaxf(v11, 0.f);
            }
            long i0 = (long)row0 * N + col;
            long i1 = (long)(row0 + 8) * N + col;
            if (OUTF) {
                *(float2*)&Cf[i0] = make_float2(v00, v01);
                *(float2*)&Cf[i1] = make_float2(v10, v11);
            }
            if (OUTB) {
                __half h0, l0, h1, l1;
                split2h(v00, &h0, &l0); split2h(v01, &h1, &l1);
                *(__half2*)&Ch_[i0] = __half2(h0, h1);
                *(__half2*)&Cl_[i0] = __half2(l0, l1);
                split2h(v10, &h0, &l0); split2h(v11, &h1, &l1);
                *(__half2*)&Ch_[i1] = __half2(h0, h1);
                *(__half2*)&Cl_[i1] = __half2(l0, l1);
            }
        }
    }
}

// ---------------- single merged weight prep: transpose + fp16 ----------------
__device__ __forceinline__ void wsplit_tile_xy(const float* __restrict__ W,
                                               __half* __restrict__ oh,
                                               int K, int N, int tx32, int ty32) {
    __shared__ float s[32][33];
    int bx = tx32 * 32, by = ty32 * 32;
    int tx = threadIdx.x, ty = threadIdx.y;
#pragma unroll
    for (int r = 0; r < 32; r += 8)
        s[ty + r][tx] = W[(long)(by + ty + r) * N + bx + tx];
    __syncthreads();
#pragma unroll
    for (int r = 0; r < 32; r += 8) {
        float v = s[tx][ty + r];
        long o = (long)(bx + ty + r) * K + by + tx;
        oh[o] = __float2half_rn(v);
    }
}

__global__ void k_wsplit_all(const float* __restrict__ Wq, const float* __restrict__ Wk,
                             const float* __restrict__ Wv, const float* __restrict__ Wo,
                             const float* __restrict__ W1, const float* __restrict__ W2,
                             __half* __restrict__ oh) {
    int z = blockIdx.z, l = z / 6, w = z % 6;
    long lo = (long)l * WL;
    if (w < 4) {
        if (blockIdx.x >= 16) return;
        const float* W = (w == 0 ? Wq : w == 1 ? Wk : w == 2 ? Wv : Wo) + (long)l * D_ * D_;
        wsplit_tile_xy(W, oh + lo + (long)w * D_ * D_, D_, D_, blockIdx.x, blockIdx.y);
    } else if (w == 4) {
        wsplit_tile_xy(W1 + (long)l * D_ * H_, oh + lo + OFF_W1, D_, H_, blockIdx.x, blockIdx.y);
    } else {
        wsplit_tile_xy(W2 + (long)l * H_ * D_, oh + lo + OFF_W2, H_, D_, blockIdx.y, blockIdx.x);
    }
}

__global__ void k_bpack(const float* __restrict__ bq, const float* __restrict__ bk,
                        const float* __restrict__ bv, float* __restrict__ out) {
    int i = blockIdx.x * 256 + threadIdx.x;
    if (i >= L_ * 3 * D_) return;
    int l = i / (3 * D_), r = (i / D_) % 3, d = i % D_;
    const float* s = (r == 0) ? bq : (r == 1) ? bk : bv;
    out[i] = s[l * D_ + d];
}

// ---------------- embedding, fused ----------------
__global__ void k_embed2(const int* __restrict__ x, const float* __restrict__ tok,
                         const float* __restrict__ pos, float* __restrict__ h,
                         float* __restrict__ e, __half* __restrict__ eh,
                         __half* __restrict__ el) {
    int i = blockIdx.x * blockDim.x + threadIdx.x;
    if (i >= NBTD) return;
    int d = i % D_, bt = i / D_, t = bt % T_;
    float s = rsqrtf((float)D_);
    float p = pos[t * D_ + d] * s;
    float hv = tok[(long)x[bt] * D_ + d] * s + p;
    h[i] = hv;
    float ev = hv + p;
    e[i] = ev;
    split2h(ev, &eh[i], &el[i]);
}

__global__ void k_ew_all(const float* __restrict__ wb, float* __restrict__ ew) {
    int t = blockIdx.x, li = blockIdx.y, j = threadIdx.x;
    bool valid = (j <= t);
    float w = valid ? wb[(long)li*T_*T_ + (long)t*T_ + (t - j)] : -1e30f;
    __shared__ float sm[64];
    sm[j] = w; __syncthreads();
    for (int off = 32; off > 0; off >>= 1) {
        if (j < off) sm[j] = fmaxf(sm[j], sm[j + off]);
        __syncthreads();
    }
    ew[(long)li*T_*WIN + t*WIN + j] = valid ? expf(w - sm[0]) : 0.f;
}

__global__ void k_kmax_part(const float* __restrict__ K, float* __restrict__ part) {
    int b = blockIdx.y, z = blockIdx.x, d = threadIdx.x;
    float m = -INFINITY;
    int t0 = z * (T_/32);
#pragma unroll 4
    for (int t = t0; t < t0 + T_/32; t++)
        m = fmaxf(m, K[((long)b*T_ + t)*D_ + d]);
    part[(b*32 + z)*D_ + d] = m;
}
__global__ void k_kmax_red(const float* __restrict__ part, float* __restrict__ kmax) {
    int b = blockIdx.x, d = threadIdx.x;
    float m = -INFINITY;
#pragma unroll
    for (int z = 0; z < 32; z++) m = fmaxf(m, part[(b*32 + z)*D_ + d]);
    kmax[b*D_ + d] = m;
}

// ---------------- tiled banded AFT ----------------
#define TBB 64
#define DBB 32
__global__ void __launch_bounds__(256, 3)
k_band3(const float* __restrict__ Qf, const float* __restrict__ Kf,
        const float* __restrict__ Vf, const float* __restrict__ kmax,
        const float* __restrict__ ew,
        __half* __restrict__ Yh, __half* __restrict__ Yl) {
    __shared__ float2 sp[127 * DBB];
    __shared__ float  sw[TBB * WIN];
    int t0 = blockIdx.x * TBB;
    int b  = blockIdx.y;
    int d0 = blockIdx.z * DBB;
    int tid = threadIdx.x;

    for (int i = tid; i < 127 * DBB; i += 256) {
        int r = i / DBB, dd = i % DBB;
        int u = t0 - 63 + r;
        if (u >= 0) {
            long idx = ((long)b*T_ + u)*D_ + d0 + dd;
            float ek = expf(Kf[idx] - kmax[b*D_ + d0 + dd]);
            sp[i] = make_float2(ek, ek * Vf[idx]);
        } else {
            sp[i] = make_float2(0.f, 0.f);
        }
    }
    for (int i = tid; i < TBB * WIN; i += 256)
        sw[i] = ew[(long)(t0 + i/WIN)*WIN + (i % WIN)];
    __syncthreads();

    int dd = tid & 31, tq = tid >> 5;
    int tb = tq * 8;

    float2 win[8];
#pragma unroll
    for (int i = 0; i < 8; i++) win[i] = sp[(tb + i + 63)*DBB + dd];

    float num[8] = {}, den[8] = {};
#pragma unroll 8
    for (int j = 0; j < WIN; j++) {
#pragma unroll
        for (int i = 0; i < 8; i++) {
            float w = sw[(tb + i)*WIN + j];
            num[i] = fmaf(w, win[i].y, num[i]);
            den[i] = fmaf(w, win[i].x, den[i]);
        }
        if (j < WIN - 1) {
#pragma unroll
            for (int i = 7; i >= 1; i--) win[i] = win[i-1];
            win[0] = sp[(tb + 62 - j)*DBB + dd];
        }
    }

#pragma unroll
    for (int i = 0; i < 8; i++) {
        int t = t0 + tb + i;
        long idx = ((long)b*T_ + t)*D_ + d0 + dd;
        float q = Qf[idx];
        float sig = 1.f / (1.f + expf(-q));
        float y = sig * num[i] / (den[i] + 1e-9f);
        split2h(y, &Yh[idx], &Yl[idx]);
    }
}

// ---------------- LayerNorm(X + R), optional pos-fusion ----------------
template<int OUTB, int POS>
__global__ void k_resid_ln(const float* __restrict__ X, const float* __restrict__ R,
                           const float* __restrict__ g, const float* __restrict__ bta,
                           float* __restrict__ out,
                           __half* __restrict__ oh, __half* __restrict__ ol,
                           const float* __restrict__ pos, float* __restrict__ e) {
    int row = blockIdx.x, tid = threadIdx.x;
    long base = (long)row * D_;
    float x0 = X[base + tid]       + R[base + tid];
    float x1 = X[base + tid + 256] + R[base + tid + 256];
    __shared__ float2 red[256];
    red[tid] = make_float2(x0 + x1, x0*x0 + x1*x1);
    __syncthreads();
    for (int off = 128; off > 0; off >>= 1) {
        if (tid < off) {
            red[tid].x += red[tid+off].x;
            red[tid].y += red[tid+off].y;
        }
        __syncthreads();
    }
    float mean = red[0].x * (1.f/D_);
    float var  = red[0].y * (1.f/D_) - mean*mean;
    float rs = rsqrtf(var + 1e-5f);
    float o0 = (x0 - mean)*rs*g[tid]       + bta[tid];
    float o1 = (x1 - mean)*rs*g[tid + 256] + bta[tid + 256];
    out[base + tid]       = o0;
    out[base + tid + 256] = o1;
    if (POS) {
        int t = row % T_;
        float s = rsqrtf((float)D_);
        float e0 = o0 + pos[(long)t*D_ + tid] * s;
        float e1 = o1 + pos[(long)t*D_ + tid + 256] * s;
        e[base + tid]       = e0;
        e[base + tid + 256] = e1;
        split2h(e0, &oh[base + tid],       &ol[base + tid]);
        split2h(e1, &oh[base + tid + 256], &ol[base + tid + 256]);
    } else if (OUTB) {
        split2h(o0, &oh[base + tid],       &ol[base + tid]);
        split2h(o1, &oh[base + tid + 256], &ol[base + tid + 256]);
    }
}

// ---------------- orchestration ----------------
extern "C" void kernel_launch(void* const* d_in, const int* in_sizes, int n_in,
                              void* d_out, int out_size) {
    const int*   x     = (const int*)  d_in[0];
    const float* tok   = (const float*)d_in[1];
    const float* pos   = (const float*)d_in[2];
    const float* Wq    = (const float*)d_in[3];
    const float* bq    = (const float*)d_in[4];
    const float* Wk    = (const float*)d_in[5];
    const float* bk    = (const float*)d_in[6];
    const float* Wv    = (const float*)d_in[7];
    const float* bv    = (const float*)d_in[8];
    const float* Wo    = (const float*)d_in[9];
    const float* bo    = (const float*)d_in[10];
    const float* wbias = (const float*)d_in[11];
    const float* lng   = (const float*)d_in[12];
    const float* lnb   = (const float*)d_in[13];
    const float* W1    = (const float*)d_in[14];
    const float* b1    = (const float*)d_in[15];
    const float* W2    = (const float*)d_in[16];
    const float* b2    = (const float*)d_in[17];
    float* H = (float*)d_out;

    float *E, *QKV, *A, *AOf, *EW, *KP, *KM, *BP;
    __half *Eh, *El, *Yh, *Yl, *AOh, *AOl, *F1h, *F1l, *Wth;
    cudaGetSymbolAddress((void**)&E,   g_E);
    cudaGetSymbolAddress((void**)&QKV, g_QKV);
    cudaGetSymbolAddress((void**)&A,   g_A);
    cudaGetSymbolAddress((void**)&AOf, g_AOf);
    cudaGetSymbolAddress((void**)&EW,  g_ew);
    cudaGetSymbolAddress((void**)&KP,  g_kpart);
    cudaGetSymbolAddress((void**)&KM,  g_kmax);
    cudaGetSymbolAddress((void**)&BP,  g_bpack);
    cudaGetSymbolAddress((void**)&Eh,  g_Eh);  cudaGetSymbolAddress((void**)&El,  g_El);
    cudaGetSymbolAddress((void**)&Yh,  g_Yh);  cudaGetSymbolAddress((void**)&Yl,  g_Yl);
    cudaGetSymbolAddress((void**)&AOh, g_AOh); cudaGetSymbolAddress((void**)&AOl, g_AOl);
    cudaGetSymbolAddress((void**)&F1h, g_F1h); cudaGetSymbolAddress((void**)&F1l, g_F1l);
    cudaGetSymbolAddress((void**)&Wth, g_Wth);

    cudaFuncSetAttribute(tc_gemm<0,1,0>, cudaFuncAttributeMaxDynamicSharedMemorySize, DSM_BYTES);
    cudaFuncSetAttribute(tc_gemm<1,0,1>, cudaFuncAttributeMaxDynamicSharedMemorySize, DSM_BYTES);

    const int EL_BLK = 256;
    const int EL_GRID = (NBTD + EL_BLK - 1) / EL_BLK;
    dim3 wblk(32, 8);

    float* Qf = QKV;
    float* Kf = QKV + (long)NBTD;
    float* Vf = QKV + 2L*NBTD;

    // launch 1..3: prep; launch 4 = layer-0 QKV GEMM (ncu window target)
    k_wsplit_all<<<dim3(64, 16, L_*6), wblk>>>(Wq, Wk, Wv, Wo, W1, W2, Wth);
    k_bpack<<<(L_*3*D_ + 255)/256, 256>>>(bq, bk, bv, BP);
    k_embed2<<<EL_GRID, EL_BLK>>>(x, tok, pos, H, E, Eh, El);

    bool ew_done = false;

    for (int l = 0; l < L_; l++) {
        long lo = (long)l * WL;
        const float* gi  = lng + l*D_;
        const float* bi  = lnb + l*D_;

        tc_gemm<0,1,0><<<dim3(D_/128, MT/128, 3), 256, DSM_BYTES>>>(
            Eh, El, Wth + lo, BP + (long)l*3*D_,
            QKV, nullptr, nullptr, MT, D_, D_,
            (long)D_*D_, (long)D_, (long)NBTD);

        if (!ew_done) {
            k_ew_all<<<dim3(T_, L_), WIN>>>(wbias, EW);
            ew_done = true;
        }

        k_kmax_part<<<dim3(32, B_), D_>>>(Kf, KP);
        k_kmax_red<<<B_, D_>>>(KP, KM);

        k_band3<<<dim3(T_/TBB, B_, D_/DBB), 256>>>(Qf, Kf, Vf, KM, EW + (long)l*T_*WIN, Yh, Yl);

        tc_gemm<0,1,0><<<dim3(D_/128, MT/128, 1), 256, DSM_BYTES>>>(
            Yh, Yl, Wth + lo + OFF_WO, bo + (long)l*D_,
            A, nullptr, nullptr, MT, D_, D_, 0, 0, 0);

        k_resid_ln<1,0><<<MT, 256>>>(A, E, gi, bi, AOf, AOh, AOl, nullptr, nullptr);

        tc_gemm<1,0,1><<<dim3(H_/128, MT/128, 1), 256, DSM_BYTES>>>(
            AOh, AOl, Wth + lo + OFF_W1, b1 + (long)l*H_,
            nullptr, F1h, F1l, MT, H_, D_, 0, 0, 0);

        tc_gemm<0,1,0><<<dim3(D_/128, MT/128, 1), 256, DSM_BYTES>>>(
            F1h, F1l, Wth + lo + OFF_W2, b2 + (long)l*D_,
            A, nullptr, nullptr, MT, D_, H_, 0, 0, 0);

        if (l < L_ - 1) {
            k_resid_ln<1,1><<<MT, 256>>>(A, AOf, gi, bi, H, Eh, El, pos, E);
        } else {
            k_resid_ln<0,0><<<MT, 256>>>(A, AOf, gi, bi, H, nullptr, nullptr, nullptr, nullptr);
        }
    }
}

// round 16
// speedup vs baseline: 1.9538x; 1.4685x over previous
#include <cuda_runtime.h>
#include <cuda_fp16.h>
#include <math.h>
#include <stdint.h>

#define B_   4
#define T_   1024
#define D_   512
#define H_   2048
#define L_   6
#define WIN  64
#define MT   (B_*T_)          // 4096 rows
#define NBTD (B_*T_*D_)       // 2,097,152

#define WL   (4*D_*D_ + D_*H_ + H_*D_)
#define OFF_WQ 0
#define OFF_WK (D_*D_)
#define OFF_WV (2*D_*D_)
#define OFF_WO (3*D_*D_)
#define OFF_W1 (4*D_*D_)
#define OFF_W2 (4*D_*D_ + D_*H_)

// ---------------- scratch (static __device__, alloc-free) ----------------
__device__ __align__(16) float g_E[NBTD];
__device__ __align__(16) float g_QKV[3*NBTD];
__device__ __align__(16) float g_A[NBTD];
__device__ __align__(16) float g_AOf[NBTD];
__device__ __align__(16) __half g_Eh[NBTD];
__device__ __align__(16) __half g_Yh[NBTD];
__device__ __align__(16) __half g_AOh[NBTD];
__device__ __align__(16) __half g_F1h[MT*H_];
__device__ __align__(16) __half g_Wth[L_*WL];      // weights fp16, [N,K]
__device__ __align__(16) float g_bpack[L_*3*D_];
__device__ float g_ew[L_*T_*WIN];
__device__ float g_kpart[B_*32*D_];
__device__ float g_kmax[B_*D_];

// ---------------- helpers ----------------
__device__ __forceinline__ uint32_t smem_u32(const void* p) {
    uint32_t a;
    asm("{ .reg .u64 t; cvta.to.shared.u64 t, %1; cvt.u32.u64 %0, t; }" : "=r"(a) : "l"(p));
    return a;
}
__device__ __forceinline__ void cpa16(uint32_t s, const void* g) {
    asm volatile("cp.async.cg.shared.global [%0], [%1], 16;" :: "r"(s), "l"(g));
}
__device__ __forceinline__ void ldmx4(uint32_t* r, uint32_t addr) {
    asm volatile("ldmatrix.sync.aligned.m8n8.x4.shared.b16 {%0,%1,%2,%3}, [%4];"
        : "=r"(r[0]), "=r"(r[1]), "=r"(r[2]), "=r"(r[3]) : "r"(addr));
}
__device__ __forceinline__ void mma16816h(float* c, const uint32_t* a, uint32_t b0, uint32_t b1) {
    asm volatile("mma.sync.aligned.m16n8k16.row.col.f32.f16.f16.f32 "
        "{%0,%1,%2,%3}, {%4,%5,%6,%7}, {%8,%9}, {%0,%1,%2,%3};"
        : "+f"(c[0]), "+f"(c[1]), "+f"(c[2]), "+f"(c[3])
        : "r"(a[0]), "r"(a[1]), "r"(a[2]), "r"(a[3]), "r"(b0), "r"(b1));
}

// ---------------- HMMA GEMM: single-term fp16 ----------------
// 256 threads, 8 warps (warp tile 32x64), 4-stage pipeline, 64KB smem -> 2 CTAs/SM.
#define STAGES 4
#define SSTAGE 16384
#define SA_  0
#define SB_  8192
#define DSM_BYTES (STAGES*SSTAGE)

template<int RELU, int OUTF, int OUTB>
__global__ void __launch_bounds__(256, 2)
tc_gemm(const __half* __restrict__ Ah_, const __half* __restrict__ Bh_,
        const float* __restrict__ bias_, float* Cf_, __half* Ch_,
        int M, int N, int K, long sB, long sBias, long sC) {
    extern __shared__ __align__(1024) char dsm[];
    int t = threadIdx.x;
    int wid = t >> 5, l = t & 31;
    int wy = wid & 3, wx = wid >> 2;       // warp tile: rows wy*32, cols wx*64
    int z = blockIdx.z;
    int bn = blockIdx.x * 128, bm = blockIdx.y * 128;

    const __half* Ahp = Ah_;
    const __half* Bhp = Bh_ + (long)z * sB;
    const float* bias = bias_ + (long)z * sBias;
    float* Cf = Cf_ ? (Cf_ + (long)z * sC) : nullptr;

    uint32_t sbase = smem_u32(dsm);

    int ra = t >> 2, kb = t & 3;
    int rb2 = ra + 64;
    long gA0 = (long)(bm + ra)  * K + kb * 8;
    long gA1 = (long)(bm + rb2) * K + kb * 8;
    long gB0 = (long)(bn + ra)  * K + kb * 8;
    long gB1 = (long)(bn + rb2) * K + kb * 8;
    uint32_t sO0 = (uint32_t)((ra  >> 3) * 512 + kb * 128 + (ra  & 7) * 16);
    uint32_t sO1 = (uint32_t)((rb2 >> 3) * 512 + kb * 128 + (rb2 & 7) * 16);

    auto load_stage = [&](int st, int kc) {
        uint32_t sb = sbase + st * SSTAGE;
        cpa16(sb + SA_ + sO0, Ahp + gA0 + kc);
        cpa16(sb + SA_ + sO1, Ahp + gA1 + kc);
        cpa16(sb + SB_ + sO0, Bhp + gB0 + kc);
        cpa16(sb + SB_ + sO1, Bhp + gB1 + kc);
    };

    uint32_t lr = (uint32_t)((l & 7) * 16);
    uint32_t offA[2][2], offB[4][2];
#pragma unroll
    for (int mi = 0; mi < 2; mi++)
#pragma unroll
        for (int ks = 0; ks < 2; ks++) {
            int tr = wy*4 + mi*2 + ((l >> 3) & 1);
            int tk = ks*2 + ((l >> 4) & 1);
            offA[mi][ks] = (uint32_t)((tr*4 + tk) * 128) + lr;
        }
#pragma unroll
    for (int j = 0; j < 4; j++)
#pragma unroll
        for (int ks = 0; ks < 2; ks++) {
            int tn = wx*8 + 2*j + ((l >> 4) & 1);
            int tk = ks*2 + ((l >> 3) & 1);
            offB[j][ks] = (uint32_t)((tn*4 + tk) * 128) + lr;
        }

    int nk = K >> 5;
    load_stage(0, 0);   asm volatile("cp.async.commit_group;");
    load_stage(1, 32);  asm volatile("cp.async.commit_group;");
    load_stage(2, 64);  asm volatile("cp.async.commit_group;");
    asm volatile("cp.async.wait_group 2;");
    __syncthreads();

    float acc[2][8][4] = {};

    for (int kt = 0; kt < nk; kt++) {
        if (kt + 3 < nk) load_stage((kt + 3) & 3, (kt + 3) * 32);
        asm volatile("cp.async.commit_group;");

        uint32_t sb = sbase + (kt & 3) * SSTAGE;
#pragma unroll
        for (int ks = 0; ks < 2; ks++) {
            uint32_t aa[2][4], bb[4][4];
#pragma unroll
            for (int mi = 0; mi < 2; mi++)
                ldmx4(aa[mi], sb + SA_ + offA[mi][ks]);
#pragma unroll
            for (int j = 0; j < 4; j++)
                ldmx4(bb[j], sb + SB_ + offB[j][ks]);
#pragma unroll
            for (int mi = 0; mi < 2; mi++)
#pragma unroll
                for (int j = 0; j < 4; j++) {
                    mma16816h(acc[mi][2*j],   aa[mi], bb[j][0], bb[j][1]);
                    mma16816h(acc[mi][2*j+1], aa[mi], bb[j][2], bb[j][3]);
                }
        }
        asm volatile("cp.async.wait_group 2;");
        __syncthreads();
    }

    int gid = l >> 2, tg = l & 3;
#pragma unroll
    for (int mi = 0; mi < 2; mi++) {
        int row0 = bm + wy*32 + mi*16 + gid;
#pragma unroll
        for (int nt = 0; nt < 8; nt++) {
            int col = bn + wx*64 + nt*8 + tg*2;
            float b0v = bias[col], b1v = bias[col + 1];
            float v00 = acc[mi][nt][0] + b0v, v01 = acc[mi][nt][1] + b1v;
            float v10 = acc[mi][nt][2] + b0v, v11 = acc[mi][nt][3] + b1v;
            if (RELU) {
                v00 = fmaxf(v00, 0.f); v01 = fmaxf(v01, 0.f);
                v10 = fmaxf(v10, 0.f); v11 = fmaxf(v11, 0.f);
            }
            long i0 = (long)row0 * N + col;
            long i1 = (long)(row0 + 8) * N + col;
            if (OUTF) {
                *(float2*)&Cf[i0] = make_float2(v00, v01);
                *(float2*)&Cf[i1] = make_float2(v10, v11);
            }
            if (OUTB) {
                *(__half2*)&Ch_[i0] = __half2(__float2half_rn(v00), __float2half_rn(v01));
                *(__half2*)&Ch_[i1] = __half2(__float2half_rn(v10), __float2half_rn(v11));
            }
        }
    }
}

// ---------------- weight prep: transpose + fp16 ----------------
__device__ __forceinline__ void wsplit_tile_xy(const float* __restrict__ W,
                                               __half* __restrict__ oh,
                                               int K, int N, int tx32, int ty32) {
    __shared__ float s[32][33];
    int bx = tx32 * 32, by = ty32 * 32;
    int tx = threadIdx.x, ty = threadIdx.y;
#pragma unroll
    for (int r = 0; r < 32; r += 8)
        s[ty + r][tx] = W[(long)(by + ty + r) * N + bx + tx];
    __syncthreads();
#pragma unroll
    for (int r = 0; r < 32; r += 8) {
        float v = s[tx][ty + r];
        long o = (long)(bx + ty + r) * K + by + tx;
        oh[o] = __float2half_rn(v);
    }
}

__global__ void k_wsplit_all(const float* __restrict__ Wq, const float* __restrict__ Wk,
                             const float* __restrict__ Wv, const float* __restrict__ Wo,
                             const float* __restrict__ W1, const float* __restrict__ W2,
                             __half* __restrict__ oh) {
    int z = blockIdx.z, l = z / 6, w = z % 6;
    long lo = (long)l * WL;
    if (w < 4) {
        if (blockIdx.x >= 16) return;
        const float* W = (w == 0 ? Wq : w == 1 ? Wk : w == 2 ? Wv : Wo) + (long)l * D_ * D_;
        wsplit_tile_xy(W, oh + lo + (long)w * D_ * D_, D_, D_, blockIdx.x, blockIdx.y);
    } else if (w == 4) {
        wsplit_tile_xy(W1 + (long)l * D_ * H_, oh + lo + OFF_W1, D_, H_, blockIdx.x, blockIdx.y);
    } else {
        wsplit_tile_xy(W2 + (long)l * H_ * D_, oh + lo + OFF_W2, H_, D_, blockIdx.y, blockIdx.x);
    }
}

__global__ void k_bpack(const float* __restrict__ bq, const float* __restrict__ bk,
                        const float* __restrict__ bv, float* __restrict__ out) {
    int i = blockIdx.x * 256 + threadIdx.x;
    if (i >= L_ * 3 * D_) return;
    int l = i / (3 * D_), r = (i / D_) % 3, d = i % D_;
    const float* s = (r == 0) ? bq : (r == 1) ? bk : bv;
    out[i] = s[l * D_ + d];
}

// ---------------- embedding, fused ----------------
__global__ void k_embed2(const int* __restrict__ x, const float* __restrict__ tok,
                         const float* __restrict__ pos, float* __restrict__ h,
                         float* __restrict__ e, __half* __restrict__ eh) {
    int i = blockIdx.x * blockDim.x + threadIdx.x;
    if (i >= NBTD) return;
    int d = i % D_, bt = i / D_, t = bt % T_;
    float s = rsqrtf((float)D_);
    float p = pos[t * D_ + d] * s;
    float hv = tok[(long)x[bt] * D_ + d] * s + p;
    h[i] = hv;
    float ev = hv + p;
    e[i] = ev;
    eh[i] = __float2half_rn(ev);
}

__global__ void k_ew_all(const float* __restrict__ wb, float* __restrict__ ew) {
    int t = blockIdx.x, li = blockIdx.y, j = threadIdx.x;
    bool valid = (j <= t);
    float w = valid ? wb[(long)li*T_*T_ + (long)t*T_ + (t - j)] : -1e30f;
    __shared__ float sm[64];
    sm[j] = w; __syncthreads();
    for (int off = 32; off > 0; off >>= 1) {
        if (j < off) sm[j] = fmaxf(sm[j], sm[j + off]);
        __syncthreads();
    }
    ew[(long)li*T_*WIN + t*WIN + j] = valid ? expf(w - sm[0]) : 0.f;
}

__global__ void k_kmax_part(const float* __restrict__ K, float* __restrict__ part) {
    int b = blockIdx.y, z = blockIdx.x, d = threadIdx.x;
    float m = -INFINITY;
    int t0 = z * (T_/32);
#pragma unroll 4
    for (int t = t0; t < t0 + T_/32; t++)
        m = fmaxf(m, K[((long)b*T_ + t)*D_ + d]);
    part[(b*32 + z)*D_ + d] = m;
}
__global__ void k_kmax_red(const float* __restrict__ part, float* __restrict__ kmax) {
    int b = blockIdx.x, d = threadIdx.x;
    float m = -INFINITY;
#pragma unroll
    for (int z = 0; z < 32; z++) m = fmaxf(m, part[(b*32 + z)*D_ + d]);
    kmax[b*D_ + d] = m;
}

// ---------------- tiled banded AFT ----------------
#define TBB 64
#define DBB 32
__global__ void __launch_bounds__(256, 3)
k_band3(const float* __restrict__ Qf, const float* __restrict__ Kf,
        const float* __restrict__ Vf, const float* __restrict__ kmax,
        const float* __restrict__ ew, __half* __restrict__ Yh) {
    __shared__ float2 sp[127 * DBB];
    __shared__ float  sw[TBB * WIN];
    int t0 = blockIdx.x * TBB;
    int b  = blockIdx.y;
    int d0 = blockIdx.z * DBB;
    int tid = threadIdx.x;

    for (int i = tid; i < 127 * DBB; i += 256) {
        int r = i / DBB, dd = i % DBB;
        int u = t0 - 63 + r;
        if (u >= 0) {
            long idx = ((long)b*T_ + u)*D_ + d0 + dd;
            float ek = expf(Kf[idx] - kmax[b*D_ + d0 + dd]);
            sp[i] = make_float2(ek, ek * Vf[idx]);
        } else {
            sp[i] = make_float2(0.f, 0.f);
        }
    }
    for (int i = tid; i < TBB * WIN; i += 256)
        sw[i] = ew[(long)(t0 + i/WIN)*WIN + (i % WIN)];
    __syncthreads();

    int dd = tid & 31, tq = tid >> 5;
    int tb = tq * 8;

    float2 win[8];
#pragma unroll
    for (int i = 0; i < 8; i++) win[i] = sp[(tb + i + 63)*DBB + dd];

    float num[8] = {}, den[8] = {};
#pragma unroll 8
    for (int j = 0; j < WIN; j++) {
#pragma unroll
        for (int i = 0; i < 8; i++) {
            float w = sw[(tb + i)*WIN + j];
            num[i] = fmaf(w, win[i].y, num[i]);
            den[i] = fmaf(w, win[i].x, den[i]);
        }
        if (j < WIN - 1) {
#pragma unroll
            for (int i = 7; i >= 1; i--) win[i] = win[i-1];
            win[0] = sp[(tb + 62 - j)*DBB + dd];
        }
    }

#pragma unroll
    for (int i = 0; i < 8; i++) {
        int t = t0 + tb + i;
        long idx = ((long)b*T_ + t)*D_ + d0 + dd;
        float q = Qf[idx];
        float sig = 1.f / (1.f + expf(-q));
        float y = sig * num[i] / (den[i] + 1e-9f);
        Yh[idx] = __float2half_rn(y);
    }
}

// ---------------- LayerNorm(X + R), optional pos-fusion ----------------
template<int OUTB, int POS>
__global__ void k_resid_ln(const float* __restrict__ X, const float* __restrict__ R,
                           const float* __restrict__ g, const float* __restrict__ bta,
                           float* __restrict__ out, __half* __restrict__ oh,
                           const float* __restrict__ pos, float* __restrict__ e) {
    int row = blockIdx.x, tid = threadIdx.x;
    long base = (long)row * D_;
    float x0 = X[base + tid]       + R[base + tid];
    float x1 = X[base + tid + 256] + R[base + tid + 256];
    __shared__ float2 red[256];
    red[tid] = make_float2(x0 + x1, x0*x0 + x1*x1);
    __syncthreads();
    for (int off = 128; off > 0; off >>= 1) {
        if (tid < off) {
            red[tid].x += red[tid+off].x;
            red[tid].y += red[tid+off].y;
        }
        __syncthreads();
    }
    float mean = red[0].x * (1.f/D_);
    float var  = red[0].y * (1.f/D_) - mean*mean;
    float rs = rsqrtf(var + 1e-5f);
    float o0 = (x0 - mean)*rs*g[tid]       + bta[tid];
    float o1 = (x1 - mean)*rs*g[tid + 256] + bta[tid + 256];
    out[base + tid]       = o0;
    out[base + tid + 256] = o1;
    if (POS) {
        int t = row % T_;
        float s = rsqrtf((float)D_);
        float e0 = o0 + pos[(long)t*D_ + tid] * s;
        float e1 = o1 + pos[(long)t*D_ + tid + 256] * s;
        e[base + tid]       = e0;
        e[base + tid + 256] = e1;
        oh[base + tid]       = __float2half_rn(e0);
        oh[base + tid + 256] = __float2half_rn(e1);
    } else if (OUTB) {
        oh[base + tid]       = __float2half_rn(o0);
        oh[base + tid + 256] = __float2half_rn(o1);
    }
}

// ---------------- orchestration ----------------
extern "C" void kernel_launch(void* const* d_in, const int* in_sizes, int n_in,
                              void* d_out, int out_size) {
    const int*   x     = (const int*)  d_in[0];
    const float* tok   = (const float*)d_in[1];
    const float* pos   = (const float*)d_in[2];
    const float* Wq    = (const float*)d_in[3];
    const float* bq    = (const float*)d_in[4];
    const float* Wk    = (const float*)d_in[5];
    const float* bk    = (const float*)d_in[6];
    const float* Wv    = (const float*)d_in[7];
    const float* bv    = (const float*)d_in[8];
    const float* Wo    = (const float*)d_in[9];
    const float* bo    = (const float*)d_in[10];
    const float* wbias = (const float*)d_in[11];
    const float* lng   = (const float*)d_in[12];
    const float* lnb   = (const float*)d_in[13];
    const float* W1    = (const float*)d_in[14];
    const float* b1    = (const float*)d_in[15];
    const float* W2    = (const float*)d_in[16];
    const float* b2    = (const float*)d_in[17];
    float* H = (float*)d_out;

    float *E, *QKV, *A, *AOf, *EW, *KP, *KM, *BP;
    __half *Eh, *Yh, *AOh, *F1h, *Wth;
    cudaGetSymbolAddress((void**)&E,   g_E);
    cudaGetSymbolAddress((void**)&QKV, g_QKV);
    cudaGetSymbolAddress((void**)&A,   g_A);
    cudaGetSymbolAddress((void**)&AOf, g_AOf);
    cudaGetSymbolAddress((void**)&EW,  g_ew);
    cudaGetSymbolAddress((void**)&KP,  g_kpart);
    cudaGetSymbolAddress((void**)&KM,  g_kmax);
    cudaGetSymbolAddress((void**)&BP,  g_bpack);
    cudaGetSymbolAddress((void**)&Eh,  g_Eh);
    cudaGetSymbolAddress((void**)&Yh,  g_Yh);
    cudaGetSymbolAddress((void**)&AOh, g_AOh);
    cudaGetSymbolAddress((void**)&F1h, g_F1h);
    cudaGetSymbolAddress((void**)&Wth, g_Wth);

    cudaFuncSetAttribute(tc_gemm<0,1,0>, cudaFuncAttributeMaxDynamicSharedMemorySize, DSM_BYTES);
    cudaFuncSetAttribute(tc_gemm<1,0,1>, cudaFuncAttributeMaxDynamicSharedMemorySize, DSM_BYTES);

    const int EL_BLK = 256;
    const int EL_GRID = (NBTD + EL_BLK - 1) / EL_BLK;
    dim3 wblk(32, 8);

    float* Qf = QKV;
    float* Kf = QKV + (long)NBTD;
    float* Vf = QKV + 2L*NBTD;

    // launch 1..3: prep; launch 4 = layer-0 QKV GEMM (ncu window target)
    k_wsplit_all<<<dim3(64, 16, L_*6), wblk>>>(Wq, Wk, Wv, Wo, W1, W2, Wth);
    k_bpack<<<(L_*3*D_ + 255)/256, 256>>>(bq, bk, bv, BP);
    k_embed2<<<EL_GRID, EL_BLK>>>(x, tok, pos, H, E, Eh);

    bool ew_done = false;

    for (int l = 0; l < L_; l++) {
        long lo = (long)l * WL;
        const float* gi  = lng + l*D_;
        const float* bi  = lnb + l*D_;

        tc_gemm<0,1,0><<<dim3(D_/128, MT/128, 3), 256, DSM_BYTES>>>(
            Eh, Wth + lo, BP + (long)l*3*D_,
            QKV, nullptr, MT, D_, D_,
            (long)D_*D_, (long)D_, (long)NBTD);

        if (!ew_done) {
            k_ew_all<<<dim3(T_, L_), WIN>>>(wbias, EW);
            ew_done = true;
        }

        k_kmax_part<<<dim3(32, B_), D_>>>(Kf, KP);
        k_kmax_red<<<B_, D_>>>(KP, KM);

        k_band3<<<dim3(T_/TBB, B_, D_/DBB), 256>>>(Qf, Kf, Vf, KM, EW + (long)l*T_*WIN, Yh);

        tc_gemm<0,1,0><<<dim3(D_/128, MT/128, 1), 256, DSM_BYTES>>>(
            Yh, Wth + lo + OFF_WO, bo + (long)l*D_,
            A, nullptr, MT, D_, D_, 0, 0, 0);

        k_resid_ln<1,0><<<MT, 256>>>(A, E, gi, bi, AOf, AOh, nullptr, nullptr);

        tc_gemm<1,0,1><<<dim3(H_/128, MT/128, 1), 256, DSM_BYTES>>>(
            AOh, Wth + lo + OFF_W1, b1 + (long)l*H_,
            nullptr, F1h, MT, H_, D_, 0, 0, 0);

        tc_gemm<0,1,0><<<dim3(D_/128, MT/128, 1), 256, DSM_BYTES>>>(
            F1h, Wth + lo + OFF_W2, b2 + (long)l*D_,
            A, nullptr, MT, D_, H_, 0, 0, 0);

        if (l < L_ - 1) {
            k_resid_ln<1,1><<<MT, 256>>>(A, AOf, gi, bi, H, Eh, pos, E);
        } else {
            k_resid_ln<0,0><<<MT, 256>>>(A, AOf, gi, bi, H, nullptr, nullptr, nullptr);
        }
    }
}